// round 7
// baseline (speedup 1.0000x reference)
#include <cuda_runtime.h>
#include <math.h>
#include <stdint.h>

#define BB   64
#define TT   256
#define IDIM 512
#define HDIM 1024
#define G4   4096        // 4*HDIM
#define GRID 128         // persistent blocks (<=148, all resident)
#define CK   64          // h chunk size (K per staging tile)
#define HPAD 68          // padded row stride for Hs

// ---- device scratch ----
__device__ float    g_gates[(size_t)TT * BB * G4];  // [T][B][4H], bi+bh folded in
__device__ float    g_h[2][BB * HDIM];              // double-buffered hidden state
__device__ unsigned g_arrive;
__device__ unsigned g_gen;

// ---------------------------------------------------------------------------
// helpers
// ---------------------------------------------------------------------------
__device__ __forceinline__ float tf32r(float v) {
    uint32_t u;
    asm("cvt.rna.tf32.f32 %0, %1;" : "=r"(u) : "f"(v));
    return __uint_as_float(u);
}

__device__ __forceinline__ void mma_tf32(float d[4],
    uint32_t a0, uint32_t a1, uint32_t a2, uint32_t a3,
    uint32_t b0, uint32_t b1)
{
    asm volatile(
        "mma.sync.aligned.m16n8k8.row.col.f32.tf32.tf32.f32 "
        "{%0,%1,%2,%3},{%4,%5,%6,%7},{%8,%9},{%0,%1,%2,%3};\n"
        : "+f"(d[0]), "+f"(d[1]), "+f"(d[2]), "+f"(d[3])
        : "r"(a0), "r"(a1), "r"(a2), "r"(a3), "r"(b0), "r"(b1));
}

__device__ __forceinline__ float sigf(float x) {
    return 1.f / (1.f + __expf(-x));
}

// strong acquire load at gpu scope -- the poll side of the grid barrier
__device__ __forceinline__ unsigned ld_acq_u32(const unsigned* p) {
    unsigned v;
    asm volatile("ld.global.acquire.gpu.u32 %0, [%1];" : "=r"(v) : "l"(p) : "memory");
    return v;
}

// ---------------------------------------------------------------------------
// Phase 1: gates = x @ Wi + bi + bh   (M=16384, K=512, N=4096)  -- tf32 MMA
// 128x128 block tile, BK=16, 8 warps (2m x 4n), warp tile 64x32 (4x4 mma).
// Block (0,0) also resets the grid-barrier state (stream order guarantees
// gemm completes before the persistent kernel starts).
// ---------------------------------------------------------------------------
__global__ void __launch_bounds__(256, 2) gemm_tc_kernel(
    const float* __restrict__ X,   // [16384, 512]
    const float* __restrict__ Wi,  // [512, 4096]
    const float* __restrict__ bi,  // [4096]
    const float* __restrict__ bh)  // [4096]
{
    if (blockIdx.x == 0 && blockIdx.y == 0 && threadIdx.x == 0) {
        g_arrive = 0u;
        g_gen    = 0u;
    }

    __shared__ float As[16][132];   // [k][m] transposed, tf32-rounded
    __shared__ float Bs[16][132];   // [k][n]

    const int tid  = threadIdx.x;
    const int lane = tid & 31;
    const int w    = tid >> 5;
    const int wm   = w & 1;          // 0..1 (64 rows each)
    const int wn   = w >> 1;         // 0..3 (32 cols each)
    const int m0   = blockIdx.y * 128;
    const int n0   = blockIdx.x * 128;

    const int rowg = lane >> 2;      // 0..7
    const int kq   = lane & 3;       // 0..3

    const int aRow = tid >> 1;           // 0..127
    const int aCol = (tid & 1) * 8;      // 0 or 8
    const int bRow = tid >> 5;           // 0..7 (also +8)
    const int bCol = (tid & 31) * 4;     // 0..124

    float acc[4][4][4];
#pragma unroll
    for (int mi = 0; mi < 4; mi++)
#pragma unroll
        for (int ni = 0; ni < 4; ni++)
#pragma unroll
            for (int q = 0; q < 4; q++) acc[mi][ni][q] = 0.f;

    // prefetch k-tile 0
    float4 pa0 = *(const float4*)(X + (size_t)(m0 + aRow) * IDIM + aCol);
    float4 pa1 = *(const float4*)(X + (size_t)(m0 + aRow) * IDIM + aCol + 4);
    float4 pb0 = *(const float4*)(Wi + (size_t)bRow * G4 + n0 + bCol);
    float4 pb1 = *(const float4*)(Wi + (size_t)(bRow + 8) * G4 + n0 + bCol);

    for (int k0 = 0; k0 < IDIM; k0 += 16) {
        As[aCol + 0][aRow] = tf32r(pa0.x);
        As[aCol + 1][aRow] = tf32r(pa0.y);
        As[aCol + 2][aRow] = tf32r(pa0.z);
        As[aCol + 3][aRow] = tf32r(pa0.w);
        As[aCol + 4][aRow] = tf32r(pa1.x);
        As[aCol + 5][aRow] = tf32r(pa1.y);
        As[aCol + 6][aRow] = tf32r(pa1.z);
        As[aCol + 7][aRow] = tf32r(pa1.w);
        {
            float4 b0 = pb0, b1 = pb1;
            b0.x = tf32r(b0.x); b0.y = tf32r(b0.y); b0.z = tf32r(b0.z); b0.w = tf32r(b0.w);
            b1.x = tf32r(b1.x); b1.y = tf32r(b1.y); b1.z = tf32r(b1.z); b1.w = tf32r(b1.w);
            *(float4*)(&Bs[bRow][bCol])     = b0;
            *(float4*)(&Bs[bRow + 8][bCol]) = b1;
        }
        __syncthreads();

        if (k0 + 16 < IDIM) {
            int kn = k0 + 16;
            pa0 = *(const float4*)(X + (size_t)(m0 + aRow) * IDIM + kn + aCol);
            pa1 = *(const float4*)(X + (size_t)(m0 + aRow) * IDIM + kn + aCol + 4);
            pb0 = *(const float4*)(Wi + (size_t)(kn + bRow) * G4 + n0 + bCol);
            pb1 = *(const float4*)(Wi + (size_t)(kn + bRow + 8) * G4 + n0 + bCol);
        }

#pragma unroll
        for (int ks = 0; ks < 2; ks++) {
            const int kb = ks * 8;
            uint32_t af[4][4], bf[4][2];
#pragma unroll
            for (int mi = 0; mi < 4; mi++) {
                int r = wm * 64 + mi * 16 + rowg;
                af[mi][0] = __float_as_uint(As[kb + kq][r]);
                af[mi][1] = __float_as_uint(As[kb + kq][r + 8]);
                af[mi][2] = __float_as_uint(As[kb + kq + 4][r]);
                af[mi][3] = __float_as_uint(As[kb + kq + 4][r + 8]);
            }
#pragma unroll
            for (int ni = 0; ni < 4; ni++) {
                int c = wn * 32 + ni * 8 + rowg;
                bf[ni][0] = __float_as_uint(Bs[kb + kq][c]);
                bf[ni][1] = __float_as_uint(Bs[kb + kq + 4][c]);
            }
#pragma unroll
            for (int mi = 0; mi < 4; mi++)
#pragma unroll
                for (int ni = 0; ni < 4; ni++)
                    mma_tf32(acc[mi][ni], af[mi][0], af[mi][1], af[mi][2], af[mi][3],
                             bf[ni][0], bf[ni][1]);
        }
        __syncthreads();
    }

    // epilogue -> g_gates[t][b][n]
#pragma unroll
    for (int ni = 0; ni < 4; ni++) {
        int n = n0 + wn * 32 + ni * 8 + 2 * kq;
        float bias0 = bi[n] + bh[n];
        float bias1 = bi[n + 1] + bh[n + 1];
#pragma unroll
        for (int mi = 0; mi < 4; mi++) {
            int m  = m0 + wm * 64 + mi * 16 + rowg;
            {
                int b = m >> 8, t = m & 255;
                float2 v = make_float2(acc[mi][ni][0] + bias0, acc[mi][ni][1] + bias1);
                *(float2*)(g_gates + (size_t)(t * BB + b) * G4 + n) = v;
            }
            {
                int m2 = m + 8;
                int b = m2 >> 8, t = m2 & 255;
                float2 v = make_float2(acc[mi][ni][2] + bias0, acc[mi][ni][3] + bias1);
                *(float2*)(g_gates + (size_t)(t * BB + b) * G4 + n) = v;
            }
        }
    }
}

// ---------------------------------------------------------------------------
// Phase 2: persistent LSTM recurrence (R5-proven structure, CK=64).
// ONLY change vs R5: the barrier poll is an acquire LOAD (no L2-atomic
// serialization) instead of atomicAdd(&g_gen, 0).
// ---------------------------------------------------------------------------
__global__ void __launch_bounds__(256, 1) lstm_persist_kernel(
    const float* __restrict__ Wh,   // [1024, 4096] original layout
    float* __restrict__ out)        // Q_all | hT | cT
{
    extern __shared__ float smem[];
    float2* Wf = (float2*)smem;                 // [128 ksteps][4 ct][32 lanes]
    float*  Hs = smem + 32768;                  // 2 * 64 * HPAD floats

    const int tid  = threadIdx.x;
    const int lane = tid & 31;
    const int wid  = tid >> 5;
    const int wm   = wid & 3;    // m16 group
    const int wn   = wid >> 2;   // n16 group
    const int bx   = blockIdx.x;

    // build Wf (B-fragment order, tf32-rounded), once
    for (int e = tid; e < 128 * 4 * 32; e += 256) {
        int l  = e & 31;
        int ct = (e >> 5) & 3;
        int s  = e >> 7;
        int k  = s * 8 + (l & 3);
        int n  = ct * 8 + (l >> 2);
        int j  = bx * 8 + (n >> 2);
        int g  = n & 3;
        float v0 = Wh[(size_t)k * G4 + g * 1024 + j];
        float v1 = Wh[(size_t)(k + 4) * G4 + g * 1024 + j];
        Wf[e] = make_float2(tf32r(v0), tf32r(v1));
    }
    __syncthreads();

    const int kq   = lane & 3;
    const int rowg = lane >> 2;
    const int odd  = lane & 1;
    const int bmy  = wm * 16 + rowg + (odd ? 8 : 0);
    const int jbase = bx * 8 + wn * 4 + (kq >> 1);

    float creg[2] = {0.f, 0.f};
    const int arow = wm * 16 + rowg;

    for (int t = 0; t < TT; t++) {
        float acc[2][4] = {{0.f,0.f,0.f,0.f},{0.f,0.f,0.f,0.f}};

        const float* __restrict__ gt = g_gates + (size_t)t * BB * G4;
        float gF[2], gI[2], gA[2], gO[2];
#pragma unroll
        for (int nt = 0; nt < 2; nt++) {
            int j = jbase + nt * 2;
            gF[nt] = __ldcg(gt + (size_t)bmy * G4 + j);
            gI[nt] = __ldcg(gt + (size_t)bmy * G4 + 1024 + j);
            gA[nt] = __ldcg(gt + (size_t)bmy * G4 + 2048 + j);
            gO[nt] = __ldcg(gt + (size_t)bmy * G4 + 3072 + j);
        }

        if (t > 0) {
            // ---- grid barrier (every thread fences its own h-stores) ----
            __threadfence();
            __syncthreads();
            if (tid == 0) {
                unsigned a = atomicAdd(&g_arrive, 1u);
                if (a == GRID - 1u) {
                    g_arrive = 0u;
                    __threadfence();
                    atomicExch(&g_gen, (unsigned)t);
                } else {
                    while (ld_acq_u32(&g_gen) < (unsigned)t) { }
                }
            }
            __syncthreads();

            const float* __restrict__ hin = g_h[t & 1];

            // prefetch chunk 0 (16 floats/thread, coalesced, L2-only)
            float4 pf[4];
            {
                int fi = tid;
#pragma unroll
                for (int i = 0; i < 4; i++, fi += 256) {
                    int b   = fi >> 4;
                    int kk4 = fi & 15;
                    pf[i] = __ldcg((const float4*)(hin + (size_t)b * HDIM + kk4 * 4));
                }
            }

            int buf = 0;
            for (int ch = 0; ch < 16; ch++) {
                {
                    float* H = Hs + buf * (64 * HPAD);
                    int fi = tid;
#pragma unroll
                    for (int i = 0; i < 4; i++, fi += 256) {
                        int b   = fi >> 4;
                        int kk4 = fi & 15;
                        float4 v = pf[i];
                        v.x = tf32r(v.x); v.y = tf32r(v.y);
                        v.z = tf32r(v.z); v.w = tf32r(v.w);
                        *(float4*)(H + b * HPAD + kk4 * 4) = v;
                    }
                }
                __syncthreads();

                if (ch < 15) {
                    int k0 = (ch + 1) * CK;
                    int fi = tid;
#pragma unroll
                    for (int i = 0; i < 4; i++, fi += 256) {
                        int b   = fi >> 4;
                        int kk4 = fi & 15;
                        pf[i] = __ldcg((const float4*)(hin + (size_t)b * HDIM + k0 + kk4 * 4));
                    }
                }

                const float* H = Hs + buf * (64 * HPAD) + arow * HPAD;
#pragma unroll
                for (int ks = 0; ks < 8; ks++) {
                    int col = ks * 8 + kq;
                    uint32_t a0 = __float_as_uint(H[col]);
                    uint32_t a1 = __float_as_uint(H[8 * HPAD + col]);
                    uint32_t a2 = __float_as_uint(H[col + 4]);
                    uint32_t a3 = __float_as_uint(H[8 * HPAD + col + 4]);
                    int s = ch * 8 + ks;
#pragma unroll
                    for (int nt = 0; nt < 2; nt++) {
                        float2 bv = Wf[(s * 4 + wn * 2 + nt) * 32 + lane];
                        mma_tf32(acc[nt], a0, a1, a2, a3,
                                 __float_as_uint(bv.x), __float_as_uint(bv.y));
                    }
                }
                buf ^= 1;
            }
            __syncthreads();
        }

        // ---- epilogue: shfl-pair gates, LSTM pointwise, write h/Q ----
        float* __restrict__ hout = g_h[(t + 1) & 1];
#pragma unroll
        for (int nt = 0; nt < 2; nt++) {
            float x0 = __shfl_xor_sync(0xffffffffu, acc[nt][0], 1);
            float x1 = __shfl_xor_sync(0xffffffffu, acc[nt][1], 1);
            float x2 = __shfl_xor_sync(0xffffffffu, acc[nt][2], 1);
            float x3 = __shfl_xor_sync(0xffffffffu, acc[nt][3], 1);

            float F, I, A, O;
            if (!odd) { F = acc[nt][0]; I = acc[nt][1]; A = x0; O = x1; }
            else      { F = x2;         I = x3;         A = acc[nt][2]; O = acc[nt][3]; }

            F += gF[nt]; I += gI[nt]; A += gA[nt]; O += gO[nt];

            float f = sigf(F);
            float i = sigf(I);
            float a = tanhf(A);
            float o = sigf(O);

            float c = f * creg[nt] + i * a;
            creg[nt] = c;
            float h = o * tanhf(c);

            int j = jbase + nt * 2;
            hout[(size_t)bmy * HDIM + j] = h;
            out[((size_t)bmy * TT + t) * HDIM + j] = h;
            if (t == TT - 1) {
                size_t qsz = (size_t)BB * TT * HDIM;
                out[qsz + (size_t)bmy * HDIM + j]             = h;
                out[qsz + BB * HDIM + (size_t)bmy * HDIM + j] = c;
            }
        }
    }
}

// ---------------------------------------------------------------------------
extern "C" void kernel_launch(void* const* d_in, const int* in_sizes, int n_in,
                              void* d_out, int out_size) {
    const float* x  = (const float*)d_in[0];
    const float* Wi = (const float*)d_in[1];
    const float* bi = (const float*)d_in[2];
    const float* Wh = (const float*)d_in[3];
    const float* bh = (const float*)d_in[4];
    float* out = (float*)d_out;

    const int smem_bytes = (32768 + 2 * 64 * HPAD) * 4;   // 165,888 B
    cudaFuncSetAttribute(lstm_persist_kernel,
                         cudaFuncAttributeMaxDynamicSharedMemorySize, smem_bytes);

    gemm_tc_kernel<<<dim3(G4 / 128, (BB * TT) / 128), 256>>>(x, Wi, bi, bh);
    lstm_persist_kernel<<<GRID, 256, smem_bytes>>>(Wh, out);
}

// round 8
// speedup vs baseline: 1.0981x; 1.0981x over previous
#include <cuda_runtime.h>
#include <cuda_fp16.h>
#include <math.h>
#include <stdint.h>

#define BB    64
#define TT    256
#define IDIM  512
#define HDIM  1024
#define G4    4096        // 4*HDIM
#define GRID  128         // persistent blocks (<=148, all resident)
#define HROW  72          // padded Hs row stride in halfs (64 data + 8 pad)

// ---- device scratch ----
__device__ float    g_gates[(size_t)TT * BB * G4];  // [T][B][4H], bi+bh folded in
__device__ __half   g_h[2][BB * HDIM];              // double-buffered hidden state (fp16)
__device__ unsigned g_arrive;
__device__ unsigned g_gen;

// ---------------------------------------------------------------------------
// helpers
// ---------------------------------------------------------------------------
__device__ __forceinline__ float tf32r(float v) {
    uint32_t u;
    asm("cvt.rna.tf32.f32 %0, %1;" : "=r"(u) : "f"(v));
    return __uint_as_float(u);
}

__device__ __forceinline__ void mma_tf32(float d[4],
    uint32_t a0, uint32_t a1, uint32_t a2, uint32_t a3,
    uint32_t b0, uint32_t b1)
{
    asm volatile(
        "mma.sync.aligned.m16n8k8.row.col.f32.tf32.tf32.f32 "
        "{%0,%1,%2,%3},{%4,%5,%6,%7},{%8,%9},{%0,%1,%2,%3};\n"
        : "+f"(d[0]), "+f"(d[1]), "+f"(d[2]), "+f"(d[3])
        : "r"(a0), "r"(a1), "r"(a2), "r"(a3), "r"(b0), "r"(b1));
}

__device__ __forceinline__ void mma_f16(float d[4],
    uint32_t a0, uint32_t a1, uint32_t a2, uint32_t a3,
    uint32_t b0, uint32_t b1)
{
    asm volatile(
        "mma.sync.aligned.m16n8k16.row.col.f32.f16.f16.f32 "
        "{%0,%1,%2,%3},{%4,%5,%6,%7},{%8,%9},{%0,%1,%2,%3};\n"
        : "+f"(d[0]), "+f"(d[1]), "+f"(d[2]), "+f"(d[3])
        : "r"(a0), "r"(a1), "r"(a2), "r"(a3), "r"(b0), "r"(b1));
}

__device__ __forceinline__ float sigf(float x) {
    return 1.f / (1.f + __expf(-x));
}

// ---------------------------------------------------------------------------
// Phase 1: gates = x @ Wi + bi + bh   (M=16384, K=512, N=4096)  -- tf32 MMA
// (unchanged, proven). Block (0,0) resets the grid-barrier state.
// ---------------------------------------------------------------------------
__global__ void __launch_bounds__(256, 2) gemm_tc_kernel(
    const float* __restrict__ X,   // [16384, 512]
    const float* __restrict__ Wi,  // [512, 4096]
    const float* __restrict__ bi,  // [4096]
    const float* __restrict__ bh)  // [4096]
{
    if (blockIdx.x == 0 && blockIdx.y == 0 && threadIdx.x == 0) {
        g_arrive = 0u;
        g_gen    = 0u;
    }

    __shared__ float As[16][132];   // [k][m] transposed, tf32-rounded
    __shared__ float Bs[16][132];   // [k][n]

    const int tid  = threadIdx.x;
    const int lane = tid & 31;
    const int w    = tid >> 5;
    const int wm   = w & 1;
    const int wn   = w >> 1;
    const int m0   = blockIdx.y * 128;
    const int n0   = blockIdx.x * 128;

    const int rowg = lane >> 2;
    const int kq   = lane & 3;

    const int aRow = tid >> 1;
    const int aCol = (tid & 1) * 8;
    const int bRow = tid >> 5;
    const int bCol = (tid & 31) * 4;

    float acc[4][4][4];
#pragma unroll
    for (int mi = 0; mi < 4; mi++)
#pragma unroll
        for (int ni = 0; ni < 4; ni++)
#pragma unroll
            for (int q = 0; q < 4; q++) acc[mi][ni][q] = 0.f;

    float4 pa0 = *(const float4*)(X + (size_t)(m0 + aRow) * IDIM + aCol);
    float4 pa1 = *(const float4*)(X + (size_t)(m0 + aRow) * IDIM + aCol + 4);
    float4 pb0 = *(const float4*)(Wi + (size_t)bRow * G4 + n0 + bCol);
    float4 pb1 = *(const float4*)(Wi + (size_t)(bRow + 8) * G4 + n0 + bCol);

    for (int k0 = 0; k0 < IDIM; k0 += 16) {
        As[aCol + 0][aRow] = tf32r(pa0.x);
        As[aCol + 1][aRow] = tf32r(pa0.y);
        As[aCol + 2][aRow] = tf32r(pa0.z);
        As[aCol + 3][aRow] = tf32r(pa0.w);
        As[aCol + 4][aRow] = tf32r(pa1.x);
        As[aCol + 5][aRow] = tf32r(pa1.y);
        As[aCol + 6][aRow] = tf32r(pa1.z);
        As[aCol + 7][aRow] = tf32r(pa1.w);
        {
            float4 b0 = pb0, b1 = pb1;
            b0.x = tf32r(b0.x); b0.y = tf32r(b0.y); b0.z = tf32r(b0.z); b0.w = tf32r(b0.w);
            b1.x = tf32r(b1.x); b1.y = tf32r(b1.y); b1.z = tf32r(b1.z); b1.w = tf32r(b1.w);
            *(float4*)(&Bs[bRow][bCol])     = b0;
            *(float4*)(&Bs[bRow + 8][bCol]) = b1;
        }
        __syncthreads();

        if (k0 + 16 < IDIM) {
            int kn = k0 + 16;
            pa0 = *(const float4*)(X + (size_t)(m0 + aRow) * IDIM + kn + aCol);
            pa1 = *(const float4*)(X + (size_t)(m0 + aRow) * IDIM + kn + aCol + 4);
            pb0 = *(const float4*)(Wi + (size_t)(kn + bRow) * G4 + n0 + bCol);
            pb1 = *(const float4*)(Wi + (size_t)(kn + bRow + 8) * G4 + n0 + bCol);
        }

#pragma unroll
        for (int ks = 0; ks < 2; ks++) {
            const int kb = ks * 8;
            uint32_t af[4][4], bf[4][2];
#pragma unroll
            for (int mi = 0; mi < 4; mi++) {
                int r = wm * 64 + mi * 16 + rowg;
                af[mi][0] = __float_as_uint(As[kb + kq][r]);
                af[mi][1] = __float_as_uint(As[kb + kq][r + 8]);
                af[mi][2] = __float_as_uint(As[kb + kq + 4][r]);
                af[mi][3] = __float_as_uint(As[kb + kq + 4][r + 8]);
            }
#pragma unroll
            for (int ni = 0; ni < 4; ni++) {
                int c = wn * 32 + ni * 8 + rowg;
                bf[ni][0] = __float_as_uint(Bs[kb + kq][c]);
                bf[ni][1] = __float_as_uint(Bs[kb + kq + 4][c]);
            }
#pragma unroll
            for (int mi = 0; mi < 4; mi++)
#pragma unroll
                for (int ni = 0; ni < 4; ni++)
                    mma_tf32(acc[mi][ni], af[mi][0], af[mi][1], af[mi][2], af[mi][3],
                             bf[ni][0], bf[ni][1]);
        }
        __syncthreads();
    }

#pragma unroll
    for (int ni = 0; ni < 4; ni++) {
        int n = n0 + wn * 32 + ni * 8 + 2 * kq;
        float bias0 = bi[n] + bh[n];
        float bias1 = bi[n + 1] + bh[n + 1];
#pragma unroll
        for (int mi = 0; mi < 4; mi++) {
            int m  = m0 + wm * 64 + mi * 16 + rowg;
            {
                int b = m >> 8, t = m & 255;
                float2 v = make_float2(acc[mi][ni][0] + bias0, acc[mi][ni][1] + bias1);
                *(float2*)(g_gates + (size_t)(t * BB + b) * G4 + n) = v;
            }
            {
                int m2 = m + 8;
                int b = m2 >> 8, t = m2 & 255;
                float2 v = make_float2(acc[mi][ni][2] + bias0, acc[mi][ni][3] + bias1);
                *(float2*)(g_gates + (size_t)(t * BB + b) * G4 + n) = v;
            }
        }
    }
}

// ---------------------------------------------------------------------------
// Phase 2: persistent LSTM recurrence -- fp16 m16n8k16 mma.
// Structure identical to the proven R5 version (16 chunks/step, 1 sync each,
// atomic-spin barrier, fenced); only the datapath is fp16:
//   g_h in half, Hs staged as half (no conversion in hot loop),
//   Wf as half2 B-fragments (built once), 4 mma k-steps per 64-col chunk.
// ---------------------------------------------------------------------------
__global__ void __launch_bounds__(256, 1) lstm_persist_kernel(
    const float* __restrict__ Wh,   // [1024, 4096] original layout
    float* __restrict__ out)        // Q_all | hT | cT
{
    extern __shared__ char smem[];
    uint2*  Wf = (uint2*)smem;                       // [64 s][4 ct][32 lanes] = 64 KB
    __half* Hs = (__half*)(smem + 65536);            // 2 * 64 * HROW halfs

    const int tid  = threadIdx.x;
    const int lane = tid & 31;
    const int wid  = tid >> 5;
    const int wm   = wid & 3;    // m16 group
    const int wn   = wid >> 2;   // n16 group
    const int bx   = blockIdx.x;

    // build Wf (fp16 B-fragments for m16n8k16), once:
    //   entry e=(s,ct,l): n = ct*8 + (l>>2); k = s*16 + (l&3)*2
    //   b0 = (B[k][n], B[k+1][n]); b1 = (B[k+8][n], B[k+9][n])
    //   B[k][n] = Wh[k][g*1024 + j], j = bx*8 + (n>>2), g = n&3
    for (int e = tid; e < 64 * 4 * 32; e += 256) {
        int l  = e & 31;
        int ct = (e >> 5) & 3;
        int s  = e >> 7;
        int k  = s * 16 + (l & 3) * 2;
        int n  = ct * 8 + (l >> 2);
        int j  = bx * 8 + (n >> 2);
        int g  = n & 3;
        const float* Wcol = Wh + (size_t)g * 1024 + j;
        __half2 h0 = __floats2half2_rn(Wcol[(size_t)k * G4],
                                       Wcol[(size_t)(k + 1) * G4]);
        __half2 h1 = __floats2half2_rn(Wcol[(size_t)(k + 8) * G4],
                                       Wcol[(size_t)(k + 9) * G4]);
        uint2 v;
        v.x = *(uint32_t*)&h0;
        v.y = *(uint32_t*)&h1;
        Wf[e] = v;
    }
    __syncthreads();

    const int kq   = lane & 3;
    const int rowg = lane >> 2;
    const int odd  = lane & 1;
    const int bmy  = wm * 16 + rowg + (odd ? 8 : 0);
    const int jbase = bx * 8 + wn * 4 + (kq >> 1);

    float creg[2] = {0.f, 0.f};
    const int arow = wm * 16 + rowg;

    // staging indices: per 64x64-half chunk, each thread stores 2x 16B (8 halfs)
    const int sb  = tid >> 3;        // row 0..31 (and +32 on 2nd pass)
    const int sg  = tid & 7;         // 16B group within row (0..7)

    for (int t = 0; t < TT; t++) {
        float acc[2][4] = {{0.f,0.f,0.f,0.f},{0.f,0.f,0.f,0.f}};

        const float* __restrict__ gt = g_gates + (size_t)t * BB * G4;
        float gF[2], gI[2], gA[2], gO[2];
#pragma unroll
        for (int nt = 0; nt < 2; nt++) {
            int j = jbase + nt * 2;
            gF[nt] = __ldcg(gt + (size_t)bmy * G4 + j);
            gI[nt] = __ldcg(gt + (size_t)bmy * G4 + 1024 + j);
            gA[nt] = __ldcg(gt + (size_t)bmy * G4 + 2048 + j);
            gO[nt] = __ldcg(gt + (size_t)bmy * G4 + 3072 + j);
        }

        if (t > 0) {
            // ---- grid barrier (proven R5 form) ----
            __threadfence();
            __syncthreads();
            if (tid == 0) {
                unsigned a = atomicAdd(&g_arrive, 1u);
                if (a == GRID - 1u) {
                    g_arrive = 0u;
                    __threadfence();
                    atomicExch(&g_gen, (unsigned)t);
                } else {
                    while (atomicAdd(&g_gen, 0u) < (unsigned)t) { }
                }
            }
            __syncthreads();

            const __half* __restrict__ hin = g_h[t & 1];

            // prefetch chunk 0: 2 x uint4 per thread (16 halfs)
            uint4 pf[2];
#pragma unroll
            for (int i = 0; i < 2; i++) {
                int b = sb + i * 32;
                pf[i] = __ldcg((const uint4*)(hin + (size_t)b * HDIM + sg * 8));
            }

            int buf = 0;
            for (int ch = 0; ch < 16; ch++) {
                // store chunk to smem (raw halfs, no conversion)
                {
                    __half* H = Hs + buf * (64 * HROW);
#pragma unroll
                    for (int i = 0; i < 2; i++) {
                        int b = sb + i * 32;
                        *(uint4*)(H + b * HROW + sg * 8) = pf[i];
                    }
                }
                __syncthreads();

                // prefetch next chunk
                if (ch < 15) {
                    int k0 = (ch + 1) * 64;
#pragma unroll
                    for (int i = 0; i < 2; i++) {
                        int b = sb + i * 32;
                        pf[i] = __ldcg((const uint4*)(hin + (size_t)b * HDIM + k0 + sg * 8));
                    }
                }

                // 4 fp16 mma k-steps (k16 each) on this chunk
                const __half* H = Hs + buf * (64 * HROW) + arow * HROW;
#pragma unroll
                for (int ks = 0; ks < 4; ks++) {
                    int col = ks * 16 + kq * 2;
                    uint32_t a0 = *(const uint32_t*)(H + col);
                    uint32_t a1 = *(const uint32_t*)(H + 8 * HROW + col);
                    uint32_t a2 = *(const uint32_t*)(H + col + 8);
                    uint32_t a3 = *(const uint32_t*)(H + 8 * HROW + col + 8);
                    int s = ch * 4 + ks;
#pragma unroll
                    for (int nt = 0; nt < 2; nt++) {
                        uint2 bv = Wf[(s * 4 + wn * 2 + nt) * 32 + lane];
                        mma_f16(acc[nt], a0, a1, a2, a3, bv.x, bv.y);
                    }
                }
                buf ^= 1;
            }
            __syncthreads();
        }

        // ---- epilogue: shfl-pair gates, LSTM pointwise, write h/Q ----
        __half* __restrict__ hout = g_h[(t + 1) & 1];
#pragma unroll
        for (int nt = 0; nt < 2; nt++) {
            float x0 = __shfl_xor_sync(0xffffffffu, acc[nt][0], 1);
            float x1 = __shfl_xor_sync(0xffffffffu, acc[nt][1], 1);
            float x2 = __shfl_xor_sync(0xffffffffu, acc[nt][2], 1);
            float x3 = __shfl_xor_sync(0xffffffffu, acc[nt][3], 1);

            float F, I, A, O;
            if (!odd) { F = acc[nt][0]; I = acc[nt][1]; A = x0; O = x1; }
            else      { F = x2;         I = x3;         A = acc[nt][2]; O = acc[nt][3]; }

            F += gF[nt]; I += gI[nt]; A += gA[nt]; O += gO[nt];

            float f = sigf(F);
            float i = sigf(I);
            float a = tanhf(A);
            float o = sigf(O);

            float c = f * creg[nt] + i * a;
            creg[nt] = c;
            float h = o * tanhf(c);

            int j = jbase + nt * 2;
            hout[(size_t)bmy * HDIM + j] = __float2half(h);
            out[((size_t)bmy * TT + t) * HDIM + j] = h;
            if (t == TT - 1) {
                size_t qsz = (size_t)BB * TT * HDIM;
                out[qsz + (size_t)bmy * HDIM + j]             = h;
                out[qsz + BB * HDIM + (size_t)bmy * HDIM + j] = c;
            }
        }
    }
}

// ---------------------------------------------------------------------------
extern "C" void kernel_launch(void* const* d_in, const int* in_sizes, int n_in,
                              void* d_out, int out_size) {
    const float* x  = (const float*)d_in[0];
    const float* Wi = (const float*)d_in[1];
    const float* bi = (const float*)d_in[2];
    const float* Wh = (const float*)d_in[3];
    const float* bh = (const float*)d_in[4];
    float* out = (float*)d_out;

    const int smem_bytes = 65536 + 2 * 64 * HROW * 2;   // 83,968 B
    cudaFuncSetAttribute(lstm_persist_kernel,
                         cudaFuncAttributeMaxDynamicSharedMemorySize, smem_bytes);

    gemm_tc_kernel<<<dim3(G4 / 128, (BB * TT) / 128), 256>>>(x, Wi, bi, bh);
    lstm_persist_kernel<<<GRID, 256, smem_bytes>>>(Wh, out);
}